// round 1
// baseline (speedup 1.0000x reference)
#include <cuda_runtime.h>
#include <math.h>

#define BB 2
#define SS 2048
#define HID 1024
#define HEADS 16
#define DHEAD 64
#define INNER 1024
#define BH (BB*HEADS)

// Scratch: q, k, v, att in [B, H, S, D] layout. 16MB each.
__device__ float g_q[BB*HEADS*SS*DHEAD];
__device__ float g_k[BB*HEADS*SS*DHEAD];
__device__ float g_v[BB*HEADS*SS*DHEAD];
__device__ float g_att[BB*HEADS*SS*DHEAD];

// ---------------------------------------------------------------------------
// GEMM: C = X @ W + bias, output scattered to [B, H, S, D] layout.
// X: [4096, 1024] row-major. W: [1024, 1024] row-major. 64x64 tile, 16x16
// threads, 4x4 microtile, K-step 16.
// ---------------------------------------------------------------------------
__global__ void gemm_in_kernel(const float* __restrict__ X,
                               const float* __restrict__ W,
                               const float* __restrict__ bias,
                               float* __restrict__ out) {
    __shared__ float a_s[16][68];   // [k][m]
    __shared__ float b_s[16][68];   // [k][n]
    const int tx = threadIdx.x, ty = threadIdx.y;
    const int tid = ty * 16 + tx;
    const int m0 = blockIdx.y * 64, n0 = blockIdx.x * 64;
    float acc[4][4] = {};

    const int ak = tid & 15, ar = tid >> 4;
    const int bc = tid & 63, bk = tid >> 6;

    for (int kt = 0; kt < HID; kt += 16) {
#pragma unroll
        for (int p = 0; p < 4; p++)
            a_s[ak][ar + p * 16] = X[(size_t)(m0 + ar + p * 16) * HID + kt + ak];
#pragma unroll
        for (int p = 0; p < 4; p++)
            b_s[bk + p * 4][bc] = W[(size_t)(kt + bk + p * 4) * INNER + n0 + bc];
        __syncthreads();
#pragma unroll
        for (int k = 0; k < 16; k++) {
            float4 a = *(const float4*)&a_s[k][4 * ty];
            float4 b = *(const float4*)&b_s[k][4 * tx];
            float av[4] = {a.x, a.y, a.z, a.w};
            float bv[4] = {b.x, b.y, b.z, b.w};
#pragma unroll
            for (int i = 0; i < 4; i++)
#pragma unroll
                for (int j = 0; j < 4; j++)
                    acc[i][j] += av[i] * bv[j];
        }
        __syncthreads();
    }
#pragma unroll
    for (int i = 0; i < 4; i++)
#pragma unroll
        for (int j = 0; j < 4; j++) {
            int row = m0 + 4 * ty + i, col = n0 + 4 * tx + j;
            int b = row >> 11, s = row & 2047, h = col >> 6, d = col & 63;
            out[(((size_t)(b * HEADS + h)) * SS + s) * DHEAD + d] = acc[i][j] + bias[col];
        }
}

// ---------------------------------------------------------------------------
// Output projection: C[row,col] = sum_k att_headed[row,k] * Wo[k,col] + bo
// att is [B,H,S,D]; logical A row = b*S+s, col = h*64+d.
// ---------------------------------------------------------------------------
__global__ void gemm_out_kernel(const float* __restrict__ A,
                                const float* __restrict__ W,
                                const float* __restrict__ bias,
                                float* __restrict__ out) {
    __shared__ float a_s[16][68];
    __shared__ float b_s[16][68];
    const int tx = threadIdx.x, ty = threadIdx.y;
    const int tid = ty * 16 + tx;
    const int m0 = blockIdx.y * 64, n0 = blockIdx.x * 64;
    float acc[4][4] = {};

    const int ak = tid & 15, ar = tid >> 4;
    const int bc = tid & 63, bk = tid >> 6;

    for (int kt = 0; kt < INNER; kt += 16) {
        const int h = kt >> 6;            // K-tile of 16 lies within one head
        const int dbase = kt & 63;
#pragma unroll
        for (int p = 0; p < 4; p++) {
            int row = m0 + ar + p * 16;
            int b = row >> 11, s = row & 2047;
            a_s[ak][ar + p * 16] =
                A[(((size_t)(b * HEADS + h)) * SS + s) * DHEAD + dbase + ak];
        }
#pragma unroll
        for (int p = 0; p < 4; p++)
            b_s[bk + p * 4][bc] = W[(size_t)(kt + bk + p * 4) * HID + n0 + bc];
        __syncthreads();
#pragma unroll
        for (int k = 0; k < 16; k++) {
            float4 a = *(const float4*)&a_s[k][4 * ty];
            float4 b = *(const float4*)&b_s[k][4 * tx];
            float av[4] = {a.x, a.y, a.z, a.w};
            float bv[4] = {b.x, b.y, b.z, b.w};
#pragma unroll
            for (int i = 0; i < 4; i++)
#pragma unroll
                for (int j = 0; j < 4; j++)
                    acc[i][j] += av[i] * bv[j];
        }
        __syncthreads();
    }
#pragma unroll
    for (int i = 0; i < 4; i++)
#pragma unroll
        for (int j = 0; j < 4; j++) {
            int row = m0 + 4 * ty + i, col = n0 + 4 * tx + j;
            out[(size_t)row * HID + col] = acc[i][j] + bias[col];
        }
}

// ---------------------------------------------------------------------------
// Flash-style attention: one block per (b*h, q-tile of 64).
// Online softmax with running max/sum; P tile reuses the K smem buffer.
// scores = (q.kT + bias) * 0.125 + mask; probs = softmax; out = probs @ v.
// Dynamic smem: 3 * 64 * 68 floats = 52224 bytes.
// ---------------------------------------------------------------------------
__global__ void attn_kernel(const float* __restrict__ bias,
                            const float* __restrict__ mask) {
    extern __shared__ float sm[];
    float* qT = sm;               // qT[d*68 + q]   (d-major)
    float* kT = sm + 64 * 68;     // kT[d*68 + kc]; reused as p[q*68 + c]
    float* vs = sm + 2 * 64 * 68; // vs[c*68 + dd]

    const int tx = threadIdx.x, ty = threadIdx.y;
    const int tid = ty * 16 + tx;
    const int bh = blockIdx.y;
    const int b = bh >> 4, h = bh & 15;
    const int q0 = blockIdx.x * 64;

    const float* qp = g_q + (size_t)bh * SS * DHEAD;
    const float* kp = g_k + (size_t)bh * SS * DHEAD;
    const float* vp = g_v + (size_t)bh * SS * DHEAD;

#pragma unroll
    for (int p = 0; p < 16; p++) {
        int idx = tid + p * 256;
        int qq = idx >> 6, d = idx & 63;
        qT[d * 68 + qq] = qp[(size_t)(q0 + qq) * DHEAD + d];
    }

    float m_r[4], l_r[4], o[4][4] = {};
#pragma unroll
    for (int i = 0; i < 4; i++) { m_r[i] = -1e30f; l_r[i] = 0.f; }

    for (int kt = 0; kt < SS; kt += 64) {
        __syncthreads();  // prior-iter readers of kT/vs done
#pragma unroll
        for (int p = 0; p < 16; p++) {
            int idx = tid + p * 256;
            int r = idx >> 6, d = idx & 63;
            kT[d * 68 + r] = kp[(size_t)(kt + r) * DHEAD + d];
            vs[r * 68 + d] = vp[(size_t)(kt + r) * DHEAD + d];
        }
        __syncthreads();

        float sc[4][4] = {};
#pragma unroll
        for (int d = 0; d < 64; d++) {
            float4 a = *(const float4*)&qT[d * 68 + 4 * ty];
            float4 bb = *(const float4*)&kT[d * 68 + 4 * tx];
            float av[4] = {a.x, a.y, a.z, a.w};
            float bv[4] = {bb.x, bb.y, bb.z, bb.w};
#pragma unroll
            for (int i = 0; i < 4; i++)
#pragma unroll
                for (int j = 0; j < 4; j++)
                    sc[i][j] += av[i] * bv[j];
        }

        // bias BEFORE scale, then mask (matches reference order)
        const float* bptr = bias + ((size_t)h * SS + q0 + 4 * ty) * SS + kt + 4 * tx;
        const float* mptr = mask + ((size_t)b * SS + q0 + 4 * ty) * SS + kt + 4 * tx;
#pragma unroll
        for (int i = 0; i < 4; i++)
#pragma unroll
            for (int j = 0; j < 4; j++)
                sc[i][j] = (sc[i][j] + bptr[(size_t)i * SS + j]) * 0.125f
                           + mptr[(size_t)i * SS + j];

        // online softmax update (rows 4ty+i, reduced across the 16 tx lanes)
#pragma unroll
        for (int i = 0; i < 4; i++) {
            float rmax = fmaxf(fmaxf(sc[i][0], sc[i][1]), fmaxf(sc[i][2], sc[i][3]));
#pragma unroll
            for (int off = 8; off >= 1; off >>= 1)
                rmax = fmaxf(rmax, __shfl_xor_sync(0xffffffffu, rmax, off));
            float mnew = fmaxf(m_r[i], rmax);
            float scale = __expf(m_r[i] - mnew);
            float rs = 0.f;
#pragma unroll
            for (int j = 0; j < 4; j++) {
                float pv = __expf(sc[i][j] - mnew);
                sc[i][j] = pv;
                rs += pv;
            }
#pragma unroll
            for (int off = 8; off >= 1; off >>= 1)
                rs += __shfl_xor_sync(0xffffffffu, rs, off);
            l_r[i] = l_r[i] * scale + rs;
            m_r[i] = mnew;
#pragma unroll
            for (int j = 0; j < 4; j++) o[i][j] *= scale;
        }

        __syncthreads();  // all score-GEMM reads of kT done before P overwrite
#pragma unroll
        for (int i = 0; i < 4; i++)
            *(float4*)&kT[(4 * ty + i) * 68 + 4 * tx] =
                make_float4(sc[i][0], sc[i][1], sc[i][2], sc[i][3]);
        __syncthreads();

        // o += P @ V
#pragma unroll
        for (int c = 0; c < 64; c++) {
            float4 vv = *(const float4*)&vs[c * 68 + 4 * tx];
            float vvv[4] = {vv.x, vv.y, vv.z, vv.w};
#pragma unroll
            for (int i = 0; i < 4; i++) {
                float pi = kT[(4 * ty + i) * 68 + c];
#pragma unroll
                for (int j = 0; j < 4; j++) o[i][j] += pi * vvv[j];
            }
        }
    }

    float* op = g_att + (size_t)bh * SS * DHEAD + (size_t)q0 * DHEAD;
#pragma unroll
    for (int i = 0; i < 4; i++) {
        float inv = 1.f / l_r[i];
#pragma unroll
        for (int j = 0; j < 4; j++)
            op[(4 * ty + i) * DHEAD + 4 * tx + j] = o[i][j] * inv;
    }
}

// ---------------------------------------------------------------------------

extern "C" void kernel_launch(void* const* d_in, const int* in_sizes, int n_in,
                              void* d_out, int out_size) {
    const float* query = (const float*)d_in[0];
    const float* key_i = (const float*)d_in[1];
    const float* value = (const float*)d_in[2];
    const float* mask  = (const float*)d_in[3];
    const float* pbias = (const float*)d_in[4];
    const float* Wq = (const float*)d_in[5];
    const float* bq = (const float*)d_in[6];
    const float* Wk = (const float*)d_in[7];
    const float* bk = (const float*)d_in[8];
    const float* Wv = (const float*)d_in[9];
    const float* bv = (const float*)d_in[10];
    const float* Wo = (const float*)d_in[11];
    const float* bo = (const float*)d_in[12];
    float* out = (float*)d_out;

    float *qb, *kb, *vb, *ab;
    cudaGetSymbolAddress((void**)&qb, g_q);
    cudaGetSymbolAddress((void**)&kb, g_k);
    cudaGetSymbolAddress((void**)&vb, g_v);
    cudaGetSymbolAddress((void**)&ab, g_att);

    dim3 blk(16, 16);
    dim3 grid_gemm(INNER / 64, (BB * SS) / 64);   // (16, 64)

    gemm_in_kernel<<<grid_gemm, blk>>>(query, Wq, bq, qb);
    gemm_in_kernel<<<grid_gemm, blk>>>(key_i, Wk, bk, kb);
    gemm_in_kernel<<<grid_gemm, blk>>>(value, Wv, bv, vb);

    const int smem = 3 * 64 * 68 * (int)sizeof(float);   // 52224
    cudaFuncSetAttribute(attn_kernel, cudaFuncAttributeMaxDynamicSharedMemorySize, smem);
    dim3 grid_attn(SS / 64, BH);                  // (32, 32)
    attn_kernel<<<grid_attn, blk, smem>>>(pbias, mask);

    gemm_out_kernel<<<grid_gemm, blk>>>(ab, Wo, bo, out);
}

// round 2
// speedup vs baseline: 2.3040x; 2.3040x over previous
#include <cuda_runtime.h>
#include <math.h>
#include <stdint.h>

#define BB 2
#define SS 2048
#define HID 1024
#define HEADS 16
#define DHEAD 64
#define INNER 1024
#define BH (BB*HEADS)

// Scratch buffers (16MB each). q,k,v in [B,H,S,D]; att in [B,S,INNER].
__device__ float g_q[BB*HEADS*SS*DHEAD];
__device__ float g_k[BB*HEADS*SS*DHEAD];
__device__ float g_v[BB*HEADS*SS*DHEAD];
__device__ float g_att[BB*SS*INNER];

__device__ __forceinline__ float to_tf32(float x) {
    float r;
    asm("cvt.rna.tf32.f32 %0, %1;" : "=f"(r) : "f"(x));
    return r;
}

// D (16x8 f32) += A (16x8 tf32, row) * B (8x8 tf32, col)
__device__ __forceinline__ void mma8(float* c, const uint32_t* a, const uint32_t* b) {
    asm volatile(
        "mma.sync.aligned.m16n8k8.row.col.f32.tf32.tf32.f32 "
        "{%0,%1,%2,%3}, {%4,%5,%6,%7}, {%8,%9}, {%0,%1,%2,%3};"
        : "+f"(c[0]), "+f"(c[1]), "+f"(c[2]), "+f"(c[3])
        : "r"(a[0]), "r"(a[1]), "r"(a[2]), "r"(a[3]), "r"(b[0]), "r"(b[1]));
}

__device__ __forceinline__ uint32_t fbits(float x) { return __float_as_uint(x); }

// ---------------------------------------------------------------------------
// tf32 GEMM: C[4096 x 1024] = X[4096 x 1024] @ W[1024 x 1024] + bias.
// Block 128x128x(K-step 32), 256 threads, 8 warps (2x4), warp tile 64x32.
// SCATTER=true -> output scattered to [B,H,S,D] (for q/k/v projections).
// ---------------------------------------------------------------------------
template <bool SCATTER>
__global__ void __launch_bounds__(256)
gemm_tf32(const float* __restrict__ X, const float* __restrict__ W,
          const float* __restrict__ bias, float* __restrict__ out) {
    __shared__ float As[128][36];   // [m][k], stride 36 -> frag LDS conflict-free
    __shared__ float Bs[32][136];   // [k][n], stride 136

    const int tid  = threadIdx.x;
    const int lane = tid & 31;
    const int wid  = tid >> 5;
    const int wm   = (wid >> 2) * 64;   // warp m offset in tile
    const int wn   = (wid & 3) * 32;    // warp n offset in tile
    const int m0   = blockIdx.y * 128;
    const int n0   = blockIdx.x * 128;

    float c[4][4][4] = {};   // [mfrag][nfrag][reg]

    for (int kt = 0; kt < HID; kt += 32) {
        // Load A tile 128x32 (coalesced float4), round to tf32.
#pragma unroll
        for (int i = 0; i < 4; i++) {
            int idx = tid + i * 256;           // 0..1023
            int r = idx >> 3, c4 = (idx & 7) * 4;
            float4 v = *(const float4*)&X[(size_t)(m0 + r) * HID + kt + c4];
            float4 t = make_float4(to_tf32(v.x), to_tf32(v.y), to_tf32(v.z), to_tf32(v.w));
            *(float4*)&As[r][c4] = t;
        }
        // Load B tile 32x128.
#pragma unroll
        for (int i = 0; i < 4; i++) {
            int idx = tid + i * 256;
            int r = idx >> 5, c4 = (idx & 31) * 4;
            float4 v = *(const float4*)&W[(size_t)(kt + r) * INNER + n0 + c4];
            float4 t = make_float4(to_tf32(v.x), to_tf32(v.y), to_tf32(v.z), to_tf32(v.w));
            *(float4*)&Bs[r][c4] = t;
        }
        __syncthreads();

#pragma unroll
        for (int k8 = 0; k8 < 32; k8 += 8) {
            uint32_t af[4][4], bf[4][2];
#pragma unroll
            for (int mf = 0; mf < 4; mf++) {
                int row = wm + mf * 16 + (lane >> 2);
                int col = k8 + (lane & 3);
                af[mf][0] = fbits(As[row][col]);
                af[mf][1] = fbits(As[row + 8][col]);
                af[mf][2] = fbits(As[row][col + 4]);
                af[mf][3] = fbits(As[row + 8][col + 4]);
            }
#pragma unroll
            for (int nf = 0; nf < 4; nf++) {
                int kr  = k8 + (lane & 3);
                int col = wn + nf * 8 + (lane >> 2);
                bf[nf][0] = fbits(Bs[kr][col]);
                bf[nf][1] = fbits(Bs[kr + 4][col]);
            }
#pragma unroll
            for (int mf = 0; mf < 4; mf++)
#pragma unroll
                for (int nf = 0; nf < 4; nf++)
                    mma8(c[mf][nf], af[mf], bf[nf]);
        }
        __syncthreads();
    }

    // Epilogue: c0/c1 = (row, 2t), (row, 2t+1); c2/c3 = row+8.
#pragma unroll
    for (int mf = 0; mf < 4; mf++) {
#pragma unroll
        for (int nf = 0; nf < 4; nf++) {
            int row = m0 + wm + mf * 16 + (lane >> 2);
            int col = n0 + wn + nf * 8 + (lane & 3) * 2;
            float2 lo = make_float2(c[mf][nf][0] + bias[col], c[mf][nf][1] + bias[col + 1]);
            float2 hi = make_float2(c[mf][nf][2] + bias[col], c[mf][nf][3] + bias[col + 1]);
            if (SCATTER) {
                int b = row >> 11, s = row & 2047;
                int h = col >> 6, d = col & 63;
                float* p = out + (((size_t)(b * HEADS + h)) * SS) * DHEAD + d;
                *(float2*)&p[(size_t)s * DHEAD]       = lo;
                *(float2*)&p[(size_t)(s) * DHEAD];  // no-op keep simple
                *(float2*)(out + (((size_t)(b * HEADS + h)) * SS + s) * DHEAD + d) = lo;
                int row8 = row + 8;
                int s8 = row8 & 2047;   // b unchanged (row8>>11 == b, tiles are 128-aligned)
                *(float2*)(out + (((size_t)(b * HEADS + h)) * SS + s8) * DHEAD + d) = hi;
            } else {
                *(float2*)(out + (size_t)row * INNER + col) = lo;
                *(float2*)(out + (size_t)(row + 8) * INNER + col) = hi;
            }
        }
    }
}

// ---------------------------------------------------------------------------
// Flash attention, tf32 mma. Block = 128 threads (4 warps), 64 q-rows,
// k-tiles of 64. scores = qk*0.125 + (bias*0.125 + mask); online softmax.
// Writes [B,S,INNER].
// ---------------------------------------------------------------------------
__global__ void __launch_bounds__(128)
attn_tf32(const float* __restrict__ bias, const float* __restrict__ mask) {
    extern __shared__ float sm[];
    float* Qs = sm;                      // [64][68]
    float* KT = sm + 64 * 68;            // [64(d)][72(key)]
    float* Vs = KT + 64 * 72;            // [64(key)][72(d)]
    float* PB = Vs + 64 * 72;            // [64(q)][68] bias-combined, then P

    const int tid  = threadIdx.x;
    const int lane = tid & 31;
    const int wid  = tid >> 5;          // 0..3 -> q rows wid*16..+15
    const int bh   = blockIdx.y;
    const int b    = bh >> 4, h = bh & 15;
    const int q0   = blockIdx.x * 64;

    const float* qp = g_q + (size_t)bh * SS * DHEAD;
    const float* kp = g_k + (size_t)bh * SS * DHEAD;
    const float* vp = g_v + (size_t)bh * SS * DHEAD;

    // Load Q tile -> smem (tf32).
#pragma unroll
    for (int i = 0; i < 8; i++) {
        int idx = tid + i * 128;
        int r = idx >> 4, c4 = (idx & 15) * 4;
        float4 v = *(const float4*)&qp[(size_t)(q0 + r) * DHEAD + c4];
        float4 t = make_float4(to_tf32(v.x), to_tf32(v.y), to_tf32(v.z), to_tf32(v.w));
        *(float4*)&Qs[r * 68 + c4] = t;
    }
    __syncthreads();

    // Q fragments, register resident: 8 k-chunks x 4 regs.
    uint32_t qf[8][4];
    {
        int qrow = wid * 16 + (lane >> 2);
#pragma unroll
        for (int kk = 0; kk < 8; kk++) {
            int col = kk * 8 + (lane & 3);
            qf[kk][0] = fbits(Qs[qrow * 68 + col]);
            qf[kk][1] = fbits(Qs[(qrow + 8) * 68 + col]);
            qf[kk][2] = fbits(Qs[qrow * 68 + col + 4]);
            qf[kk][3] = fbits(Qs[(qrow + 8) * 68 + col + 4]);
        }
    }

    float mr0 = -1e30f, mr1 = -1e30f, l0 = 0.f, l1 = 0.f;
    float o[8][4] = {};   // [d-frag][reg]

    const float* bp = bias + ((size_t)h * SS + q0) * SS;
    const float* mp = mask + ((size_t)b * SS + q0) * SS;

    for (int kt = 0; kt < SS; kt += 64) {
        __syncthreads();   // prior-iter readers of KT/Vs/PB are done

        // K (transposed) and V tiles.
#pragma unroll
        for (int i = 0; i < 8; i++) {
            int idx = tid + i * 128;
            int r = idx >> 4, c4 = (idx & 15) * 4;
            float4 kv = *(const float4*)&kp[(size_t)(kt + r) * DHEAD + c4];
            KT[(c4 + 0) * 72 + r] = to_tf32(kv.x);
            KT[(c4 + 1) * 72 + r] = to_tf32(kv.y);
            KT[(c4 + 2) * 72 + r] = to_tf32(kv.z);
            KT[(c4 + 3) * 72 + r] = to_tf32(kv.w);
            float4 vv = *(const float4*)&vp[(size_t)(kt + r) * DHEAD + c4];
            float4 vt = make_float4(to_tf32(vv.x), to_tf32(vv.y), to_tf32(vv.z), to_tf32(vv.w));
            *(float4*)&Vs[r * 72 + c4] = vt;
        }
        // Combined additive term: bias*0.125 + mask -> PB.
#pragma unroll
        for (int i = 0; i < 8; i++) {
            int idx = tid + i * 128;
            int r = idx >> 4, c4 = (idx & 15) * 4;
            float4 bv = *(const float4*)&bp[(size_t)r * SS + kt + c4];
            float4 mv = *(const float4*)&mp[(size_t)r * SS + kt + c4];
            float4 cb = make_float4(bv.x * 0.125f + mv.x, bv.y * 0.125f + mv.y,
                                    bv.z * 0.125f + mv.z, bv.w * 0.125f + mv.w);
            *(float4*)&PB[r * 68 + c4] = cb;
        }
        __syncthreads();

        // scores = Q @ K^T
        float s[8][4] = {};
#pragma unroll
        for (int kk = 0; kk < 8; kk++) {
            uint32_t bf[8][2];
            int kr = kk * 8 + (lane & 3);
#pragma unroll
            for (int nf = 0; nf < 8; nf++) {
                int col = nf * 8 + (lane >> 2);
                bf[nf][0] = fbits(KT[kr * 72 + col]);
                bf[nf][1] = fbits(KT[(kr + 4) * 72 + col]);
            }
#pragma unroll
            for (int nf = 0; nf < 8; nf++)
                mma8(s[nf], qf[kk], bf[nf]);
        }

        // scale + additive term, then online softmax.
        int lr = wid * 16 + (lane >> 2);
        float tm0 = -1e30f, tm1 = -1e30f;
#pragma unroll
        for (int nf = 0; nf < 8; nf++) {
            int col = nf * 8 + (lane & 3) * 2;
            float2 a0 = *(const float2*)&PB[lr * 68 + col];
            float2 a1 = *(const float2*)&PB[(lr + 8) * 68 + col];
            s[nf][0] = s[nf][0] * 0.125f + a0.x;
            s[nf][1] = s[nf][1] * 0.125f + a0.y;
            s[nf][2] = s[nf][2] * 0.125f + a1.x;
            s[nf][3] = s[nf][3] * 0.125f + a1.y;
            tm0 = fmaxf(tm0, fmaxf(s[nf][0], s[nf][1]));
            tm1 = fmaxf(tm1, fmaxf(s[nf][2], s[nf][3]));
        }
#pragma unroll
        for (int off = 1; off <= 2; off <<= 1) {
            tm0 = fmaxf(tm0, __shfl_xor_sync(0xffffffffu, tm0, off));
            tm1 = fmaxf(tm1, __shfl_xor_sync(0xffffffffu, tm1, off));
        }
        float mn0 = fmaxf(mr0, tm0), mn1 = fmaxf(mr1, tm1);
        float sc0 = __expf(mr0 - mn0), sc1 = __expf(mr1 - mn1);
        float rs0 = 0.f, rs1 = 0.f;
#pragma unroll
        for (int nf = 0; nf < 8; nf++) {
            s[nf][0] = __expf(s[nf][0] - mn0);
            s[nf][1] = __expf(s[nf][1] - mn0);
            s[nf][2] = __expf(s[nf][2] - mn1);
            s[nf][3] = __expf(s[nf][3] - mn1);
            rs0 += s[nf][0] + s[nf][1];
            rs1 += s[nf][2] + s[nf][3];
        }
#pragma unroll
        for (int off = 1; off <= 2; off <<= 1) {
            rs0 += __shfl_xor_sync(0xffffffffu, rs0, off);
            rs1 += __shfl_xor_sync(0xffffffffu, rs1, off);
        }
        l0 = l0 * sc0 + rs0;
        l1 = l1 * sc1 + rs1;
        mr0 = mn0; mr1 = mn1;
#pragma unroll
        for (int df = 0; df < 8; df++) {
            o[df][0] *= sc0; o[df][1] *= sc0;
            o[df][2] *= sc1; o[df][3] *= sc1;
        }

        __syncthreads();   // everyone done reading PB (bias) and KT
        // Write P (tf32) into PB.
#pragma unroll
        for (int nf = 0; nf < 8; nf++) {
            int col = nf * 8 + (lane & 3) * 2;
            float2 p0 = make_float2(to_tf32(s[nf][0]), to_tf32(s[nf][1]));
            float2 p1 = make_float2(to_tf32(s[nf][2]), to_tf32(s[nf][3]));
            *(float2*)&PB[lr * 68 + col] = p0;
            *(float2*)&PB[(lr + 8) * 68 + col] = p1;
        }
        __syncthreads();

        // o += P @ V
#pragma unroll
        for (int kk = 0; kk < 8; kk++) {
            uint32_t pa[4];
            int prow = wid * 16 + (lane >> 2);
            int pcol = kk * 8 + (lane & 3);
            pa[0] = fbits(PB[prow * 68 + pcol]);
            pa[1] = fbits(PB[(prow + 8) * 68 + pcol]);
            pa[2] = fbits(PB[prow * 68 + pcol + 4]);
            pa[3] = fbits(PB[(prow + 8) * 68 + pcol + 4]);
#pragma unroll
            for (int df = 0; df < 8; df++) {
                uint32_t vb[2];
                int vr = kk * 8 + (lane & 3);
                int vc = df * 8 + (lane >> 2);
                vb[0] = fbits(Vs[vr * 72 + vc]);
                vb[1] = fbits(Vs[(vr + 4) * 72 + vc]);
                mma8(o[df], pa, vb);
            }
        }
    }

    // Epilogue -> g_att [B,S,INNER]
    float inv0 = 1.f / l0, inv1 = 1.f / l1;
    int row0 = q0 + wid * 16 + (lane >> 2);
#pragma unroll
    for (int df = 0; df < 8; df++) {
        int colg = h * 64 + df * 8 + (lane & 3) * 2;
        float2 lo = make_float2(o[df][0] * inv0, o[df][1] * inv0);
        float2 hi = make_float2(o[df][2] * inv1, o[df][3] * inv1);
        *(float2*)(g_att + ((size_t)b * SS + row0) * INNER + colg) = lo;
        *(float2*)(g_att + ((size_t)b * SS + row0 + 8) * INNER + colg) = hi;
    }
}

// ---------------------------------------------------------------------------

extern "C" void kernel_launch(void* const* d_in, const int* in_sizes, int n_in,
                              void* d_out, int out_size) {
    const float* query = (const float*)d_in[0];
    const float* key_i = (const float*)d_in[1];
    const float* value = (const float*)d_in[2];
    const float* mask  = (const float*)d_in[3];
    const float* pbias = (const float*)d_in[4];
    const float* Wq = (const float*)d_in[5];
    const float* bq = (const float*)d_in[6];
    const float* Wk = (const float*)d_in[7];
    const float* bk = (const float*)d_in[8];
    const float* Wv = (const float*)d_in[9];
    const float* bv = (const float*)d_in[10];
    const float* Wo = (const float*)d_in[11];
    const float* bo = (const float*)d_in[12];
    float* out = (float*)d_out;

    float *qb, *kb, *vb, *ab;
    cudaGetSymbolAddress((void**)&qb, g_q);
    cudaGetSymbolAddress((void**)&kb, g_k);
    cudaGetSymbolAddress((void**)&vb, g_v);
    cudaGetSymbolAddress((void**)&ab, g_att);

    dim3 grid_gemm(INNER / 128, (BB * SS) / 128);   // (8, 32)

    gemm_tf32<true><<<grid_gemm, 256>>>(query, Wq, bq, qb);
    gemm_tf32<true><<<grid_gemm, 256>>>(key_i, Wk, bk, kb);
    gemm_tf32<true><<<grid_gemm, 256>>>(value, Wv, bv, vb);

    const int smem = (64 * 68 + 64 * 72 + 64 * 72 + 64 * 68) * (int)sizeof(float); // 71680
    cudaFuncSetAttribute(attn_tf32, cudaFuncAttributeMaxDynamicSharedMemorySize, smem);
    dim3 grid_attn(SS / 64, BH);                    // (32, 32)
    attn_tf32<<<grid_attn, 128, smem>>>(pbias, mask);

    gemm_tf32<false><<<grid_gemm, 256>>>(ab, Wo, bo, out);
}

// round 3
// speedup vs baseline: 2.7337x; 1.1865x over previous
#include <cuda_runtime.h>
#include <math.h>
#include <stdint.h>

#define BB 2
#define SS 2048
#define HID 1024
#define HEADS 16
#define DHEAD 64
#define INNER 1024
#define BH (BB*HEADS)

// Scratch buffers (16MB each). q,k,v in [B,H,S,D]; att in [B,S,INNER].
__device__ float g_q[BB*HEADS*SS*DHEAD];
__device__ float g_k[BB*HEADS*SS*DHEAD];
__device__ float g_v[BB*HEADS*SS*DHEAD];
__device__ float g_att[BB*SS*INNER];

__device__ __forceinline__ float to_tf32(float x) {
    float r;
    asm("cvt.rna.tf32.f32 %0, %1;" : "=f"(r) : "f"(x));
    return r;
}

// D (16x8 f32) += A (16x8 tf32, row) * B (8x8 tf32, col)
__device__ __forceinline__ void mma8(float* c, const uint32_t* a, const uint32_t* b) {
    asm volatile(
        "mma.sync.aligned.m16n8k8.row.col.f32.tf32.tf32.f32 "
        "{%0,%1,%2,%3}, {%4,%5,%6,%7}, {%8,%9}, {%0,%1,%2,%3};"
        : "+f"(c[0]), "+f"(c[1]), "+f"(c[2]), "+f"(c[3])
        : "r"(a[0]), "r"(a[1]), "r"(a[2]), "r"(a[3]), "r"(b[0]), "r"(b[1]));
}

__device__ __forceinline__ uint32_t fbits(float x) { return __float_as_uint(x); }

// ---------------------------------------------------------------------------
// tf32 GEMM: C[4096 x 1024] = X[4096 x 1024] @ W[1024 x 1024] + bias.
// Block 128x128x(K-step 32), 256 threads, 8 warps (2x4), warp tile 64x32.
// SCATTER=true -> output scattered to [B,H,S,D] (for q/k/v projections).
// ---------------------------------------------------------------------------
template <bool SCATTER>
__global__ void __launch_bounds__(256)
gemm_tf32(const float* __restrict__ X, const float* __restrict__ W,
          const float* __restrict__ bias, float* __restrict__ out) {
    __shared__ float As[128][36];   // [m][k]
    __shared__ float Bs[32][136];   // [k][n]

    const int tid  = threadIdx.x;
    const int lane = tid & 31;
    const int wid  = tid >> 5;
    const int wm   = (wid >> 2) * 64;
    const int wn   = (wid & 3) * 32;
    const int m0   = blockIdx.y * 128;
    const int n0   = blockIdx.x * 128;

    float c[4][4][4] = {};

    for (int kt = 0; kt < HID; kt += 32) {
#pragma unroll
        for (int i = 0; i < 4; i++) {
            int idx = tid + i * 256;
            int r = idx >> 3, c4 = (idx & 7) * 4;
            float4 v = *(const float4*)&X[(size_t)(m0 + r) * HID + kt + c4];
            float4 t = make_float4(to_tf32(v.x), to_tf32(v.y), to_tf32(v.z), to_tf32(v.w));
            *(float4*)&As[r][c4] = t;
        }
#pragma unroll
        for (int i = 0; i < 4; i++) {
            int idx = tid + i * 256;
            int r = idx >> 5, c4 = (idx & 31) * 4;
            float4 v = *(const float4*)&W[(size_t)(kt + r) * INNER + n0 + c4];
            float4 t = make_float4(to_tf32(v.x), to_tf32(v.y), to_tf32(v.z), to_tf32(v.w));
            *(float4*)&Bs[r][c4] = t;
        }
        __syncthreads();

#pragma unroll
        for (int k8 = 0; k8 < 32; k8 += 8) {
            uint32_t af[4][4], bf[4][2];
#pragma unroll
            for (int mf = 0; mf < 4; mf++) {
                int row = wm + mf * 16 + (lane >> 2);
                int col = k8 + (lane & 3);
                af[mf][0] = fbits(As[row][col]);
                af[mf][1] = fbits(As[row + 8][col]);
                af[mf][2] = fbits(As[row][col + 4]);
                af[mf][3] = fbits(As[row + 8][col + 4]);
            }
#pragma unroll
            for (int nf = 0; nf < 4; nf++) {
                int kr  = k8 + (lane & 3);
                int col = wn + nf * 8 + (lane >> 2);
                bf[nf][0] = fbits(Bs[kr][col]);
                bf[nf][1] = fbits(Bs[kr + 4][col]);
            }
#pragma unroll
            for (int mf = 0; mf < 4; mf++)
#pragma unroll
                for (int nf = 0; nf < 4; nf++)
                    mma8(c[mf][nf], af[mf], bf[nf]);
        }
        __syncthreads();
    }

#pragma unroll
    for (int mf = 0; mf < 4; mf++) {
#pragma unroll
        for (int nf = 0; nf < 4; nf++) {
            int row = m0 + wm + mf * 16 + (lane >> 2);
            int col = n0 + wn + nf * 8 + (lane & 3) * 2;
            float2 lo = make_float2(c[mf][nf][0] + bias[col], c[mf][nf][1] + bias[col + 1]);
            float2 hi = make_float2(c[mf][nf][2] + bias[col], c[mf][nf][3] + bias[col + 1]);
            if (SCATTER) {
                int b = row >> 11, s = row & 2047;
                int h = col >> 6, d = col & 63;
                *(float2*)(out + (((size_t)(b * HEADS + h)) * SS + s) * DHEAD + d) = lo;
                *(float2*)(out + (((size_t)(b * HEADS + h)) * SS + s + 8) * DHEAD + d) = hi;
            } else {
                *(float2*)(out + (size_t)row * INNER + col) = lo;
                *(float2*)(out + (size_t)(row + 8) * INNER + col) = hi;
            }
        }
    }
}

// ---------------------------------------------------------------------------
// Flash attention, tf32 mma. Block = 256 threads (8 warps), 128 q-rows,
// k-tiles of 64. K kept row-major [key][d] (it IS K^T col-major for mma);
// bias/mask loaded straight to registers; P buffers are warp-private.
// ---------------------------------------------------------------------------
#define KS_STRIDE 68
#define VS_STRIDE 72
#define PS_STRIDE 68

__global__ void __launch_bounds__(256, 2)
attn_tf32(const float* __restrict__ bias, const float* __restrict__ mask) {
    extern __shared__ float sm[];
    float* Ks = sm;                          // [64][68]   = 4352
    float* Vs = sm + 64 * KS_STRIDE;         // [64][72]   = 4608
    float* Ps = Vs + 64 * VS_STRIDE;         // 8 x [16][68] = 8704

    const int tid  = threadIdx.x;
    const int lane = tid & 31;
    const int wid  = tid >> 5;               // 0..7, q rows wid*16..+15
    const int bh   = blockIdx.y;
    const int b    = bh >> 4, h = bh & 15;
    const int q0   = blockIdx.x * 128;

    const float* qp = g_q + (size_t)bh * SS * DHEAD;
    const float* kp = g_k + (size_t)bh * SS * DHEAD;
    const float* vp = g_v + (size_t)bh * SS * DHEAD;

    // Stage Q (128x64) coalesced into smem (reuses Ks/Vs region), grab
    // register fragments, then release the region for K/V.
    {
        float* Qs = sm;   // [128][68] = 8704 floats, fits in Ks+Vs region (8960)
#pragma unroll
        for (int i = 0; i < 8; i++) {
            int idx = tid + i * 256;
            int r = idx >> 4, c4 = (idx & 15) * 4;
            float4 v = *(const float4*)&qp[(size_t)(q0 + r) * DHEAD + c4];
            float4 t = make_float4(to_tf32(v.x), to_tf32(v.y), to_tf32(v.z), to_tf32(v.w));
            *(float4*)&Qs[r * 68 + c4] = t;
        }
        __syncthreads();
    }
    uint32_t qf[8][4];
    {
        const float* Qs = sm;
        int qrow = wid * 16 + (lane >> 2);
#pragma unroll
        for (int kk = 0; kk < 8; kk++) {
            int col = kk * 8 + (lane & 3);
            qf[kk][0] = fbits(Qs[qrow * 68 + col]);
            qf[kk][1] = fbits(Qs[(qrow + 8) * 68 + col]);
            qf[kk][2] = fbits(Qs[qrow * 68 + col + 4]);
            qf[kk][3] = fbits(Qs[(qrow + 8) * 68 + col + 4]);
        }
    }

    float mr0 = -1e30f, mr1 = -1e30f, l0 = 0.f, l1 = 0.f;
    float o[8][4] = {};

    const int grow0 = q0 + wid * 16 + (lane >> 2);
    const float* bp = bias + ((size_t)h * SS + grow0) * SS;   // +8 row handled below
    const float* mp = mask + ((size_t)b * SS + grow0) * SS;
    float* Pw = Ps + wid * 16 * PS_STRIDE;

    for (int kt = 0; kt < SS; kt += 64) {
        __syncthreads();   // prior readers of Ks/Vs (and Q staging) done
        // Fill K and V tiles (row-major, tf32), coalesced float4.
#pragma unroll
        for (int i = 0; i < 4; i++) {
            int idx = tid + i * 256;
            int r = idx >> 4, c4 = (idx & 15) * 4;
            float4 kv = *(const float4*)&kp[(size_t)(kt + r) * DHEAD + c4];
            *(float4*)&Ks[r * KS_STRIDE + c4] =
                make_float4(to_tf32(kv.x), to_tf32(kv.y), to_tf32(kv.z), to_tf32(kv.w));
            float4 vv = *(const float4*)&vp[(size_t)(kt + r) * DHEAD + c4];
            *(float4*)&Vs[r * VS_STRIDE + c4] =
                make_float4(to_tf32(vv.x), to_tf32(vv.y), to_tf32(vv.z), to_tf32(vv.w));
        }
        __syncthreads();

        // scores = Q @ K^T   (B fragments read directly from row-major K)
        float s[8][4] = {};
#pragma unroll
        for (int kk = 0; kk < 8; kk++) {
            int kr = kk * 8 + (lane & 3);
#pragma unroll
            for (int nf = 0; nf < 8; nf++) {
                int key = nf * 8 + (lane >> 2);
                uint32_t bf[2];
                bf[0] = fbits(Ks[key * KS_STRIDE + kr]);
                bf[1] = fbits(Ks[key * KS_STRIDE + kr + 4]);
                mma8(s[nf], qf[kk], bf);
            }
        }

        // fixup: s = s*0.125 + bias*0.125 + mask  (direct gmem loads)
        float tm0 = -1e30f, tm1 = -1e30f;
#pragma unroll
        for (int nf = 0; nf < 8; nf++) {
            int col = kt + nf * 8 + (lane & 3) * 2;
            float2 b0 = *(const float2*)&bp[col];
            float2 b1 = *(const float2*)&bp[(size_t)8 * SS + col];
            float2 m0v = *(const float2*)&mp[col];
            float2 m1v = *(const float2*)&mp[(size_t)8 * SS + col];
            s[nf][0] = (s[nf][0] + b0.x) * 0.125f + m0v.x;
            s[nf][1] = (s[nf][1] + b0.y) * 0.125f + m0v.y;
            s[nf][2] = (s[nf][2] + b1.x) * 0.125f + m1v.x;
            s[nf][3] = (s[nf][3] + b1.y) * 0.125f + m1v.y;
            tm0 = fmaxf(tm0, fmaxf(s[nf][0], s[nf][1]));
            tm1 = fmaxf(tm1, fmaxf(s[nf][2], s[nf][3]));
        }
#pragma unroll
        for (int off = 1; off <= 2; off <<= 1) {
            tm0 = fmaxf(tm0, __shfl_xor_sync(0xffffffffu, tm0, off));
            tm1 = fmaxf(tm1, __shfl_xor_sync(0xffffffffu, tm1, off));
        }
        float mn0 = fmaxf(mr0, tm0), mn1 = fmaxf(mr1, tm1);
        float sc0 = __expf(mr0 - mn0), sc1 = __expf(mr1 - mn1);
        float rs0 = 0.f, rs1 = 0.f;
#pragma unroll
        for (int nf = 0; nf < 8; nf++) {
            s[nf][0] = __expf(s[nf][0] - mn0);
            s[nf][1] = __expf(s[nf][1] - mn0);
            s[nf][2] = __expf(s[nf][2] - mn1);
            s[nf][3] = __expf(s[nf][3] - mn1);
            rs0 += s[nf][0] + s[nf][1];
            rs1 += s[nf][2] + s[nf][3];
        }
#pragma unroll
        for (int off = 1; off <= 2; off <<= 1) {
            rs0 += __shfl_xor_sync(0xffffffffu, rs0, off);
            rs1 += __shfl_xor_sync(0xffffffffu, rs1, off);
        }
        l0 = l0 * sc0 + rs0;
        l1 = l1 * sc1 + rs1;
        mr0 = mn0; mr1 = mn1;
#pragma unroll
        for (int df = 0; df < 8; df++) {
            o[df][0] *= sc0; o[df][1] *= sc0;
            o[df][2] *= sc1; o[df][3] *= sc1;
        }

        // P -> warp-private smem (no block sync needed).
        __syncwarp();
        {
            int lr = lane >> 2;
#pragma unroll
            for (int nf = 0; nf < 8; nf++) {
                int col = nf * 8 + (lane & 3) * 2;
                *(float2*)&Pw[lr * PS_STRIDE + col] =
                    make_float2(to_tf32(s[nf][0]), to_tf32(s[nf][1]));
                *(float2*)&Pw[(lr + 8) * PS_STRIDE + col] =
                    make_float2(to_tf32(s[nf][2]), to_tf32(s[nf][3]));
            }
        }
        __syncwarp();

        // o += P @ V
#pragma unroll
        for (int kk = 0; kk < 8; kk++) {
            uint32_t pa[4];
            int prow = lane >> 2;
            int pcol = kk * 8 + (lane & 3);
            pa[0] = fbits(Pw[prow * PS_STRIDE + pcol]);
            pa[1] = fbits(Pw[(prow + 8) * PS_STRIDE + pcol]);
            pa[2] = fbits(Pw[prow * PS_STRIDE + pcol + 4]);
            pa[3] = fbits(Pw[(prow + 8) * PS_STRIDE + pcol + 4]);
            int vr = kk * 8 + (lane & 3);
#pragma unroll
            for (int df = 0; df < 8; df++) {
                int vc = df * 8 + (lane >> 2);
                uint32_t vb[2];
                vb[0] = fbits(Vs[vr * VS_STRIDE + vc]);
                vb[1] = fbits(Vs[(vr + 4) * VS_STRIDE + vc]);
                mma8(o[df], pa, vb);
            }
        }
    }

    // Epilogue -> g_att [B,S,INNER]
    float inv0 = 1.f / l0, inv1 = 1.f / l1;
#pragma unroll
    for (int df = 0; df < 8; df++) {
        int colg = h * 64 + df * 8 + (lane & 3) * 2;
        float2 lo = make_float2(o[df][0] * inv0, o[df][1] * inv0);
        float2 hi = make_float2(o[df][2] * inv1, o[df][3] * inv1);
        *(float2*)(g_att + ((size_t)b * SS + grow0) * INNER + colg) = lo;
        *(float2*)(g_att + ((size_t)b * SS + grow0 + 8) * INNER + colg) = hi;
    }
}

// ---------------------------------------------------------------------------

extern "C" void kernel_launch(void* const* d_in, const int* in_sizes, int n_in,
                              void* d_out, int out_size) {
    const float* query = (const float*)d_in[0];
    const float* key_i = (const float*)d_in[1];
    const float* value = (const float*)d_in[2];
    const float* mask  = (const float*)d_in[3];
    const float* pbias = (const float*)d_in[4];
    const float* Wq = (const float*)d_in[5];
    const float* bq = (const float*)d_in[6];
    const float* Wk = (const float*)d_in[7];
    const float* bk = (const float*)d_in[8];
    const float* Wv = (const float*)d_in[9];
    const float* bv = (const float*)d_in[10];
    const float* Wo = (const float*)d_in[11];
    const float* bo = (const float*)d_in[12];
    float* out = (float*)d_out;

    float *qb, *kb, *vb, *ab;
    cudaGetSymbolAddress((void**)&qb, g_q);
    cudaGetSymbolAddress((void**)&kb, g_k);
    cudaGetSymbolAddress((void**)&vb, g_v);
    cudaGetSymbolAddress((void**)&ab, g_att);

    dim3 grid_gemm(INNER / 128, (BB * SS) / 128);   // (8, 32)

    gemm_tf32<true><<<grid_gemm, 256>>>(query, Wq, bq, qb);
    gemm_tf32<true><<<grid_gemm, 256>>>(key_i, Wk, bk, kb);
    gemm_tf32<true><<<grid_gemm, 256>>>(value, Wv, bv, vb);

    const int smem = (64 * KS_STRIDE + 64 * VS_STRIDE + 128 * PS_STRIDE) * (int)sizeof(float); // 70656
    cudaFuncSetAttribute(attn_tf32, cudaFuncAttributeMaxDynamicSharedMemorySize, smem);
    dim3 grid_attn(SS / 128, BH);                   // (16, 32)
    attn_tf32<<<grid_attn, 256, smem>>>(pbias, mask);

    gemm_tf32<false><<<grid_gemm, 256>>>(ab, Wo, bo, out);
}